// round 16
// speedup vs baseline: 6.8032x; 1.0163x over previous
#include <cuda_runtime.h>
#include <cuda_bf16.h>
#include <math.h>
#include <stdint.h>

#define HID   128
#define NUSER 100000
#define NPOST 50000
#define ETOT  1650000
#define SCAN_CHUNK 4096

typedef __nv_bfloat16 bf16;
typedef __nv_bfloat162 bf162;

// ---------------- scratch ----------------
__device__ float g_hA_user[(NUSER + 128) * HID];
__device__ float g_hB_user[(NUSER + 128) * HID];
__device__ float g_hB_post[(NPOST + 128) * HID];
__device__ bf16  g_accUH[(size_t)(NUSER + 128) * 512];
__device__ bf16  g_accUL[(size_t)(NUSER + 128) * 512];
__device__ bf16  g_accPH[(size_t)(NPOST + 128) * 512];
__device__ bf16  g_accPL[(size_t)(NPOST + 128) * 512];
__device__ bf16  g_BuH[128 * 512];
__device__ bf16  g_BuL[128 * 512];
__device__ bf16  g_BpH[2 * 128 * 512];
__device__ bf16  g_BpL[2 * 128 * 512];
__device__ bf16  g_WuserH[128 * 64];
__device__ bf16  g_WuserL[128 * 64];

__device__ float g_aU [NUSER * 12];      // layer-0 user alphas (stride 12)
__device__ float g_aP [NPOST * 6];       // layer-0 post alphas (stride 6, slots 2..5 used)
__device__ float g_aU2[(NUSER + 128) * 4];  // layer-1 user alphas (stride 4)
__device__ float g_aP2[(NPOST + 128) * 4];  // layer-1 post alphas (stride 4)
__device__ float g_uU [2 * 12 * HID];
__device__ float g_uP [2 * 6 * HID];
__device__ float g_bc [2 * 3 * HID];
__device__ float g_wt [768 * 4];
__device__ float g_cv [4];
__device__ int   g_cnt[320004];
__device__ int   g_off[320004];
__device__ int   g_cur[320004];
__device__ int   g_csr[ETOT];
__device__ int   g_bsum[128];

// ---------------- streams/events ----------------
static cudaStream_t g_s2;
static cudaEvent_t g_evF, g_evJ, g_evPack, g_evW, g_evAP0, g_evAgg0, g_evPost;
namespace {
struct InitStreams {
    InitStreams() {
        cudaStreamCreateWithFlags(&g_s2, cudaStreamNonBlocking);
        cudaEventCreateWithFlags(&g_evF, cudaEventDisableTiming);
        cudaEventCreateWithFlags(&g_evJ, cudaEventDisableTiming);
        cudaEventCreateWithFlags(&g_evPack, cudaEventDisableTiming);
        cudaEventCreateWithFlags(&g_evW, cudaEventDisableTiming);
        cudaEventCreateWithFlags(&g_evAP0, cudaEventDisableTiming);
        cudaEventCreateWithFlags(&g_evAgg0, cudaEventDisableTiming);
        cudaEventCreateWithFlags(&g_evPost, cudaEventDisableTiming);
    }
};
InitStreams g_init_streams;
}

// ================= descriptors =================
struct GSeg {
    const float* A = nullptr;
    const bf16* Abh = nullptr;
    const bf16* Abl = nullptr;
    const bf16* Bh = nullptr;
    const bf16* Bl = nullptr;
    const float* bias = nullptr;
    float* C = nullptr;
    const float* uvec = nullptr;
    float* aout = nullptr;
    int M = 0, K = 0, relu = 0, nv = 0, ctaBase = 0, abf = 0;
    const float* cW1 = nullptr;
    const float* cW2 = nullptr;
    const float* cB1 = nullptr;
    const float* cB2 = nullptr;
    float* cOut = nullptr;
    int clf = 0;
};
struct E5 {
    const int* src[5];
    const int* dst[5];
    int rb[5];
    int ebase[6];
};
struct AggAll {
    const float* aS[5];
    const float* aD[5];
    const float* h[5];
    bf16* acch[5];
    bf16* accl[5];
    int ss[5], sd[5], accStride[5], colOfs[5], offBase[5];
    int base[6];
};

// ================= helpers =================
__device__ __forceinline__ uint32_t smem_u32(const void* p) {
    uint32_t a;
    asm("{ .reg .u64 t; cvta.to.shared.u64 t, %1; cvt.u32.u64 %0, t; }" : "=r"(a) : "l"(p));
    return a;
}
__device__ __forceinline__ void cpa16(uint32_t saddr, const void* g) {
    asm volatile("cp.async.cg.shared.global [%0], [%1], 16;" :: "r"(saddr), "l"(g));
}
__device__ __forceinline__ void split2(float2 a, uint32_t& hi, uint32_t& lo) {
    asm("cvt.rn.bf16x2.f32 %0, %1, %2;" : "=r"(hi) : "f"(a.y), "f"(a.x));
    float h0 = __uint_as_float(hi << 16);
    float h1 = __uint_as_float(hi & 0xFFFF0000u);
    float r0 = a.x - h0, r1 = a.y - h1;
    asm("cvt.rn.bf16x2.f32 %0, %1, %2;" : "=r"(lo) : "f"(r1), "f"(r0));
}

#define MMA16816(c, a0, a1, a2, a3, b0, b1) \
    asm volatile("mma.sync.aligned.m16n8k16.row.col.f32.bf16.bf16.f32 " \
        "{%0,%1,%2,%3}, {%4,%5,%6,%7}, {%8,%9}, {%0,%1,%2,%3};" \
        : "+f"((c)[0]), "+f"((c)[1]), "+f"((c)[2]), "+f"((c)[3]) \
        : "r"(a0), "r"(a1), "r"(a2), "r"(a3), "r"(b0), "r"(b1))

// ================= batched cp.async-pipelined bf16x3 HMMA GEMM =================
__global__ __launch_bounds__(256, 2) void hgemm_b(GSeg s0, GSeg s1, GSeg s2)
{
    extern __shared__ __align__(16) char smem_dyn[];
    __shared__ float sU[12][128];
    __shared__ float sPart[2][128][12];
    __shared__ float sw2s[64], sb1s[64];

    int bid = blockIdx.x;
    GSeg s = s0;
    if (bid >= s1.ctaBase) s = s1;
    if (bid >= s2.ctaBase) s = s2;
    const int row0 = (bid - s.ctaBase) * 128;
    const int K = s.K;
    const int abf = s.abf;

    const int tid = threadIdx.x;
    const int wid = tid >> 5, lane = tid & 31;
    const int g = lane >> 2, tq = lane & 3;
    const int wm = (wid & 3) * 32, wn = (wid >> 2) * 64;

    const int lrow = tid >> 1;
    const int half = tid & 1;
    int arow = row0 + lrow; if (arow >= s.M) arow = s.M - 1;
    const float* aP  = s.A   ? s.A   + (size_t)arow * K + half * 16 : nullptr;
    const bf16* aHp2 = s.Abh ? s.Abh + (size_t)arow * K + half * 16 : nullptr;
    const bf16* aLp2 = s.Abl ? s.Abl + (size_t)arow * K + half * 16 : nullptr;
    const bf16* bHp = s.Bh + (size_t)lrow * K + half * 16;
    const bf16* bLp = s.Bl + (size_t)lrow * K + half * 16;

    const uint32_t sb = smem_u32(smem_dyn);
    const uint32_t aoffF = (uint32_t)(lrow * 160 + half * 64);
    const uint32_t aoffB = (uint32_t)(lrow * 80 + half * 32);
    const uint32_t boff  = (uint32_t)(lrow * 80 + half * 32);

    float acc[2][8][4];
    #pragma unroll
    for (int mt = 0; mt < 2; mt++)
        #pragma unroll
        for (int nt = 0; nt < 8; nt++)
            #pragma unroll
            for (int q = 0; q < 4; q++) acc[mt][nt][q] = 0.f;

    const int nst = K >> 5;

    {
        if (abf) {
            uint32_t sA = sb + aoffB;
            cpa16(sA, aHp2); cpa16(sA + 16, aHp2 + 8);
            uint32_t sL = sb + 10240 + aoffB;
            cpa16(sL, aLp2); cpa16(sL + 16, aLp2 + 8);
        } else {
            uint32_t sA = sb + aoffF;
            cpa16(sA, aP); cpa16(sA + 16, aP + 4);
            cpa16(sA + 32, aP + 8); cpa16(sA + 48, aP + 12);
        }
        uint32_t sB = sb + 20480 + boff;
        cpa16(sB, bHp); cpa16(sB + 16, bHp + 8);
        uint32_t sL2 = sb + 30720 + boff;
        cpa16(sL2, bLp); cpa16(sL2 + 16, bLp + 8);
        asm volatile("cp.async.commit_group;");
    }

    for (int ch = 0; ch < nst; ch++) {
        if (ch + 1 < nst) {
            int k0 = (ch + 1) * 32;
            uint32_t base = sb + (((ch + 1) & 1) ? 40960u : 0u);
            if (abf) {
                uint32_t sA = base + aoffB;
                cpa16(sA, aHp2 + k0); cpa16(sA + 16, aHp2 + k0 + 8);
                uint32_t sL = base + 10240 + aoffB;
                cpa16(sL, aLp2 + k0); cpa16(sL + 16, aLp2 + k0 + 8);
            } else {
                uint32_t sA = base + aoffF;
                cpa16(sA, aP + k0); cpa16(sA + 16, aP + k0 + 4);
                cpa16(sA + 32, aP + k0 + 8); cpa16(sA + 48, aP + k0 + 12);
            }
            uint32_t sB = base + 20480 + boff;
            cpa16(sB, bHp + k0); cpa16(sB + 16, bHp + k0 + 8);
            uint32_t sL2 = base + 30720 + boff;
            cpa16(sL2, bLp + k0); cpa16(sL2 + 16, bLp + k0 + 8);
            asm volatile("cp.async.commit_group;");
            asm volatile("cp.async.wait_group 1;");
        } else {
            asm volatile("cp.async.wait_group 0;");
        }
        __syncthreads();

        const char* buf = smem_dyn + ((ch & 1) ? 40960 : 0);
        const bf16* pB  = (const bf16*)(buf + 20480);
        const bf16* pBl = (const bf16*)(buf + 30720);

        #pragma unroll
        for (int kk = 0; kk < 32; kk += 16) {
            const int kc = kk + tq * 2;
            uint32_t aH[2][4], aL[2][4];
            if (abf) {
                const bf16* pAh = (const bf16*)buf;
                const bf16* pAl = (const bf16*)(buf + 10240);
                #pragma unroll
                for (int mt = 0; mt < 2; mt++) {
                    int r = wm + mt * 16 + g;
                    aH[mt][0] = *(const uint32_t*)(pAh + r * 40 + kc);
                    aH[mt][1] = *(const uint32_t*)(pAh + (r + 8) * 40 + kc);
                    aH[mt][2] = *(const uint32_t*)(pAh + r * 40 + kc + 8);
                    aH[mt][3] = *(const uint32_t*)(pAh + (r + 8) * 40 + kc + 8);
                    aL[mt][0] = *(const uint32_t*)(pAl + r * 40 + kc);
                    aL[mt][1] = *(const uint32_t*)(pAl + (r + 8) * 40 + kc);
                    aL[mt][2] = *(const uint32_t*)(pAl + r * 40 + kc + 8);
                    aL[mt][3] = *(const uint32_t*)(pAl + (r + 8) * 40 + kc + 8);
                }
            } else {
                const float* pA = (const float*)buf;
                #pragma unroll
                for (int mt = 0; mt < 2; mt++) {
                    int r = wm + mt * 16 + g;
                    split2(*(const float2*)(pA + r * 40 + kc),           aH[mt][0], aL[mt][0]);
                    split2(*(const float2*)(pA + (r + 8) * 40 + kc),     aH[mt][1], aL[mt][1]);
                    split2(*(const float2*)(pA + r * 40 + kc + 8),       aH[mt][2], aL[mt][2]);
                    split2(*(const float2*)(pA + (r + 8) * 40 + kc + 8), aH[mt][3], aL[mt][3]);
                }
            }
            #pragma unroll
            for (int nt = 0; nt < 8; nt++) {
                int n = wn + nt * 8 + g;
                uint32_t bh0 = *(const uint32_t*)(pB  + n * 40 + kc);
                uint32_t bh1 = *(const uint32_t*)(pB  + n * 40 + kc + 8);
                uint32_t bl0 = *(const uint32_t*)(pBl + n * 40 + kc);
                uint32_t bl1 = *(const uint32_t*)(pBl + n * 40 + kc + 8);
                #pragma unroll
                for (int mt = 0; mt < 2; mt++) {
                    MMA16816(acc[mt][nt], aH[mt][0], aH[mt][1], aH[mt][2], aH[mt][3], bh0, bh1);
                    MMA16816(acc[mt][nt], aH[mt][0], aH[mt][1], aH[mt][2], aH[mt][3], bl0, bl1);
                    MMA16816(acc[mt][nt], aL[mt][0], aL[mt][1], aL[mt][2], aL[mt][3], bh0, bh1);
                }
            }
        }
        __syncthreads();
    }

    // ---- finalize (bias + relu) ----
    #pragma unroll
    for (int mt = 0; mt < 2; mt++)
        #pragma unroll
        for (int nt = 0; nt < 8; nt++) {
            int col = wn + nt * 8 + tq * 2;
            float b0 = s.bias[col], b1 = s.bias[col + 1];
            acc[mt][nt][0] += b0; acc[mt][nt][1] += b1;
            acc[mt][nt][2] += b0; acc[mt][nt][3] += b1;
            if (s.relu) {
                acc[mt][nt][0] = fmaxf(acc[mt][nt][0], 0.f);
                acc[mt][nt][1] = fmaxf(acc[mt][nt][1], 0.f);
                acc[mt][nt][2] = fmaxf(acc[mt][nt][2], 0.f);
                acc[mt][nt][3] = fmaxf(acc[mt][nt][3], 0.f);
            }
        }

    if (s.clf) {
        float (*sW1t)[132] = (float(*)[132])smem_dyn;
        float* zp = (float*)(smem_dyn + 64 * 132 * 4);
        for (int i = tid; i < 128 * 64; i += 256) {
            int d = i >> 6, j = i & 63;
            sW1t[j][d] = s.cW1[i];
        }
        if (tid < 64) { sw2s[tid] = s.cW2[tid]; sb1s[tid] = s.cB1[tid]; }
        float cacc = 0.f;
        const int whalf = wid >> 2;
        #pragma unroll
        for (int pass = 0; pass < 2; pass++) {
            __syncthreads();
            #pragma unroll 4
            for (int jj = 0; jj < 32; jj++) {
                int j = pass * 32 + jj;
                #pragma unroll
                for (int mt = 0; mt < 2; mt++) {
                    float p0 = 0.f, p1 = 0.f;
                    #pragma unroll
                    for (int nt = 0; nt < 8; nt++) {
                        int col = wn + nt * 8 + tq * 2;
                        float w0 = sW1t[j][col], w1 = sW1t[j][col + 1];
                        p0 += acc[mt][nt][0] * w0 + acc[mt][nt][1] * w1;
                        p1 += acc[mt][nt][2] * w0 + acc[mt][nt][3] * w1;
                    }
                    p0 += __shfl_down_sync(0xffffffffu, p0, 1, 4);
                    p0 += __shfl_down_sync(0xffffffffu, p0, 2, 4);
                    p1 += __shfl_down_sync(0xffffffffu, p1, 1, 4);
                    p1 += __shfl_down_sync(0xffffffffu, p1, 2, 4);
                    if (tq == 0) {
                        zp[(whalf * 128 + wm + mt * 16 + g) * 33 + jj] = p0;
                        zp[(whalf * 128 + wm + mt * 16 + g + 8) * 33 + jj] = p1;
                    }
                }
            }
            __syncthreads();
            {
                int row = tid >> 1, hf = tid & 1;
                #pragma unroll 8
                for (int jj = hf * 16; jj < hf * 16 + 16; jj++) {
                    int j = pass * 32 + jj;
                    float z = zp[row * 33 + jj] + zp[(128 + row) * 33 + jj] + sb1s[j];
                    z = z > 0.f ? z : 0.f;
                    cacc += z * sw2s[j];
                }
            }
        }
        cacc += __shfl_down_sync(0xffffffffu, cacc, 1, 2);
        int row = tid >> 1;
        if ((tid & 1) == 0 && row0 + row < s.M)
            s.cOut[row0 + row] = cacc + s.cB2[0];
        return;
    }

    // ---- store C ----
    #pragma unroll
    for (int mt = 0; mt < 2; mt++) {
        int r = row0 + wm + mt * 16 + g;
        #pragma unroll
        for (int nt = 0; nt < 8; nt++) {
            int col = wn + nt * 8 + tq * 2;
            if (r < s.M)
                *(float2*)&s.C[(size_t)r * 128 + col] = make_float2(acc[mt][nt][0], acc[mt][nt][1]);
            if (r + 8 < s.M)
                *(float2*)&s.C[(size_t)(r + 8) * 128 + col] = make_float2(acc[mt][nt][2], acc[mt][nt][3]);
        }
    }

    // ---- fused alpha ----
    const int nv = s.nv;
    if (nv > 0) {
        for (int i = tid; i < nv * 128; i += 256)
            sU[i >> 7][i & 127] = s.uvec[i];
        __syncthreads();
        const int whalf = wid >> 2;
        for (int v = 0; v < nv; v++) {
            #pragma unroll
            for (int mt = 0; mt < 2; mt++) {
                float p0 = 0.f, p1 = 0.f;
                #pragma unroll
                for (int nt = 0; nt < 8; nt++) {
                    int col = wn + nt * 8 + tq * 2;
                    float u0 = sU[v][col], u1 = sU[v][col + 1];
                    p0 += acc[mt][nt][0] * u0 + acc[mt][nt][1] * u1;
                    p1 += acc[mt][nt][2] * u0 + acc[mt][nt][3] * u1;
                }
                p0 += __shfl_down_sync(0xffffffffu, p0, 1, 4);
                p0 += __shfl_down_sync(0xffffffffu, p0, 2, 4);
                p1 += __shfl_down_sync(0xffffffffu, p1, 1, 4);
                p1 += __shfl_down_sync(0xffffffffu, p1, 2, 4);
                if (tq == 0) {
                    sPart[whalf][wm + mt * 16 + g][v] = p0;
                    sPart[whalf][wm + mt * 16 + g + 8][v] = p1;
                }
            }
        }
        __syncthreads();
        for (int i = tid; i < 128 * nv; i += 256) {
            int row = i / nv, v = i - row * nv;
            int gr = row0 + row;
            if (gr < s.M)
                s.aout[(size_t)gr * nv + v] = sPart[0][row][v] + sPart[1][row][v];
        }
    }
}
#define HG_SMEM 81920

// ================= precompute =================
__device__ __forceinline__ void split1(float v, bf16* hp, bf16* lp) {
    bf16 h = __float2bfloat16(v);
    *hp = h;
    *lp = __float2bfloat16(v - __bfloat162float(h));
}

__global__ void precompute_all(const float* __restrict__ Wsrc, const float* __restrict__ Wdst,
                               const float* __restrict__ asrc, const float* __restrict__ adst,
                               const float* __restrict__ gbias,
                               float* uU, float* uP, float* bcomb,
                               const float* __restrict__ Wu,
                               bf16* WuH, bf16* WuL)
{
    int b = blockIdx.x;
    int t = threadIdx.x;
    if (b >= 23) {
        const int NU = 128 * 64;
        int i = (b - 23) * 256 + t;
        if (i >= NU) return;
        int c = i / 64, k = i % 64;
        bf16 hv, lv; split1(Wu[(size_t)k * 128 + c], &hv, &lv);
        WuH[i] = hv; WuL[i] = lv;
        return;
    }
    if (b >= 20) {
        int i = (b - 20) * 256 + t;
        if (i < 768) {
            int l = i / 384, tt = (i % 384) / 128, c = i & 127;
            const float* bl = gbias + (size_t)l * 5 * HID;
            float v;
            if (tt == 0)      v = bl[3*HID + c] + bl[4*HID + c];
            else if (tt == 1) v = bl[0*HID + c] + bl[1*HID + c];
            else              v = bl[2*HID + c];
            bcomb[i] = v;
        }
        return;
    }
    const int srcT[5] = {0,0,1,0,0}, dstT[5] = {1,1,2,0,0};
    const int soff[5] = {0,2,0,4,6}, doff[5] = {2,4,0,8,10};
    const int nv[3] = {12,6,0};
    int l = b / 10, rr = (b % 10) / 2, side = b & 1;
    int type = side ? dstT[rr] : srcT[rr];
    if (type == 2) return;
    float* uT[2] = {uU, uP};
    const float* W = (side ? Wdst : Wsrc) + (size_t)(l*5 + rr) * HID * 256;
    const float* a = (side ? adst : asrc) + (size_t)(l*5 + rr) * 256;
    int slot = side ? doff[rr] : soff[rr];
    float* dest = uT[type] + ((size_t)l * nv[type] + slot) * HID;
    int h = t >> 7, d = t & 127;
    const float* wp = W + (size_t)d * 256 + h * HID;
    const float* ap = a + h * HID;
    float s = 0.f;
    #pragma unroll 8
    for (int c = 0; c < HID; c++) s += wp[c] * ap[c];
    dest[h * HID + d] = s;
}

__global__ void fold_wtilde(const float* __restrict__ Wpost, const float* __restrict__ bpost,
                            const float* __restrict__ uP, float* __restrict__ wt,
                            float* __restrict__ cv)
{
    int i = blockIdx.x * 256 + threadIdx.x;
    if (i < 768 * 4) {
        int k = i >> 2, v = i & 3;
        const float* u = uP + (size_t)(2 + v) * HID;
        const float* w = Wpost + (size_t)k * HID;
        float s = 0.f;
        #pragma unroll 8
        for (int d = 0; d < HID; d++) s += w[d] * u[d];
        wt[i] = s;
    } else if (i < 768 * 4 + 4) {
        int v = i - 768 * 4;
        const float* u = uP + (size_t)(2 + v) * HID;
        float s = 0.f;
        for (int d = 0; d < HID; d++) s += bpost[d] * u[d];
        cv[v] = s;
    }
}

__global__ void alpha_post0(const float* __restrict__ pc, const float* __restrict__ wt,
                            const float* __restrict__ cv, float* __restrict__ aP, int n)
{
    int w = (blockIdx.x * blockDim.x + threadIdx.x) >> 5;
    int lane = threadIdx.x & 31;
    if (w >= n) return;
    const float4* row = (const float4*)(pc + (size_t)w * 768);
    float s0 = 0.f, s1 = 0.f, s2 = 0.f, s3 = 0.f;
    #pragma unroll
    for (int it = 0; it < 6; it++) {
        float4 x = __ldg(row + it * 32 + lane);
        int k = (it * 32 + lane) * 4;
        float4 w0 = __ldg((const float4*)(wt + (size_t)(k + 0) * 4));
        float4 w1 = __ldg((const float4*)(wt + (size_t)(k + 1) * 4));
        float4 w2 = __ldg((const float4*)(wt + (size_t)(k + 2) * 4));
        float4 w3 = __ldg((const float4*)(wt + (size_t)(k + 3) * 4));
        s0 += x.x*w0.x + x.y*w1.x + x.z*w2.x + x.w*w3.x;
        s1 += x.x*w0.y + x.y*w1.y + x.z*w2.y + x.w*w3.y;
        s2 += x.x*w0.z + x.y*w1.z + x.z*w2.z + x.w*w3.z;
        s3 += x.x*w0.w + x.y*w1.w + x.z*w2.w + x.w*w3.w;
    }
    #pragma unroll
    for (int o = 16; o; o >>= 1) {
        s0 += __shfl_down_sync(0xffffffffu, s0, o);
        s1 += __shfl_down_sync(0xffffffffu, s1, o);
        s2 += __shfl_down_sync(0xffffffffu, s2, o);
        s3 += __shfl_down_sync(0xffffffffu, s3, o);
    }
    if (lane == 0) {
        float* o = aP + (size_t)w * 6 + 2;
        o[0] = s0 + cv[0]; o[1] = s1 + cv[1];
        o[2] = s2 + cv[2]; o[3] = s3 + cv[3];
    }
}

__global__ void pack_layerW(const float* __restrict__ gWsrc,
                            bf16* BuH, bf16* BuL, bf16* BpH, bf16* BpL)
{
    int i = blockIdx.x * 256 + threadIdx.x;
    if (i >= 3 * 128 * 512) return;
    int seg = i / (128 * 512);
    int rem = i % (128 * 512);
    int c = rem / 512;
    int k = rem % 512;
    int l = (seg == 2) ? 1 : 0;
    int rel;
    if (seg == 0) rel = (k < 256) ? 3 : 4;
    else          rel = (k < 256) ? 0 : 1;
    int kk = k & 255, h = kk >> 7, d = kk & 127;
    float v = 0.5f * gWsrc[(((size_t)(l*5 + rel) * HID + d) * 256) + h * HID + c];
    bf16 hv, lv; split1(v, &hv, &lv);
    size_t o;
    if (seg == 0)      { o = (size_t)c * 512 + k;                     BuH[o] = hv; BuL[o] = lv; }
    else               { o = ((size_t)(seg - 1) * 128 + c) * 512 + k; BpH[o] = hv; BpL[o] = lv; }
}

// ================= CSR build =================
__global__ void hist_all(E5 e, int* __restrict__ cnt)
{
    int gid = blockIdx.x * blockDim.x + threadIdx.x;
    if (gid >= e.ebase[5]) return;
    int r = 0;
    while (gid >= e.ebase[r + 1]) r++;
    int i = gid - e.ebase[r];
    atomicAdd(&cnt[e.rb[r] + __ldg(e.dst[r] + i)], 1);
}
__global__ void csr_scatter_all(E5 e, int* __restrict__ cur, int* __restrict__ csr)
{
    int gid = blockIdx.x * blockDim.x + threadIdx.x;
    if (gid >= e.ebase[5]) return;
    int r = 0;
    while (gid >= e.ebase[r + 1]) r++;
    int i = gid - e.ebase[r];
    int pos = atomicAdd(&cur[e.rb[r] + __ldg(e.dst[r] + i)], 1);
    csr[pos] = __ldg(e.src[r] + i);
}
__global__ void scan_block_kernel(int* __restrict__ cnt, int* __restrict__ off,
                                  int* __restrict__ bsum, int n)
{
    __shared__ int sh[256];
    int tid = threadIdx.x;
    int base = blockIdx.x * SCAN_CHUNK + tid * 16;
    int v[16]; int s = 0;
    #pragma unroll
    for (int i = 0; i < 16; i++) {
        int idx = base + i;
        v[i] = (idx < n) ? cnt[idx] : 0;
        if (idx < n) cnt[idx] = 0;
        s += v[i];
    }
    sh[tid] = s; __syncthreads();
    for (int o = 1; o < 256; o <<= 1) {
        int t = (tid >= o) ? sh[tid - o] : 0;
        __syncthreads(); sh[tid] += t; __syncthreads();
    }
    int run = sh[tid] - s;
    if (tid == 255) bsum[blockIdx.x] = sh[255];
    #pragma unroll
    for (int i = 0; i < 16; i++) { int idx = base + i; if (idx < n) off[idx] = run; run += v[i]; }
}
__global__ void scan_top_kernel(int* bsum, int nb)
{
    __shared__ int sh[128];
    int t = threadIdx.x;
    int v = (t < nb) ? bsum[t] : 0;
    sh[t] = v; __syncthreads();
    for (int o = 1; o < 128; o <<= 1) {
        int x = (t >= o) ? sh[t - o] : 0;
        __syncthreads(); sh[t] += x; __syncthreads();
    }
    if (t < nb) bsum[t] = sh[t] - v;
}
__global__ void scan_add_kernel(int* __restrict__ off, int* __restrict__ cur,
                                const int* __restrict__ bsum, int n)
{
    int add = bsum[blockIdx.x];
    int base = blockIdx.x * SCAN_CHUNK + threadIdx.x * 16;
    #pragma unroll
    for (int i = 0; i < 16; i++) {
        int idx = base + i;
        if (idx < n) { int v = off[idx] + add; off[idx] = v; cur[idx] = v; }
    }
}

// ================= aggregation =================
__device__ __forceinline__ float lexp(float x, float ad) {
    x += ad;
    x = x > 0.f ? x : 0.2f * x;
    return __expf(fminf(x, 60.f));
}

__device__ __forceinline__ void store4_split(bf16* hi, bf16* lo, float a, float b, float c, float d)
{
    bf16 ha, la, hb, lb, hc, lc, hd, ld;
    split1(a, &ha, &la); split1(b, &hb, &lb); split1(c, &hc, &lc); split1(d, &hd, &ld);
    ((bf162*)hi)[0] = __halves2bfloat162(ha, hb);
    ((bf162*)hi)[1] = __halves2bfloat162(hc, hd);
    ((bf162*)lo)[0] = __halves2bfloat162(la, lb);
    ((bf162*)lo)[1] = __halves2bfloat162(lc, ld);
}

__global__ void agg_all(AggAll A, const int* __restrict__ off, const int* __restrict__ csr)
{
    int w = (blockIdx.x * blockDim.x + threadIdx.x) >> 5;
    int lane = threadIdx.x & 31;
    if (w >= A.base[5]) return;
    int r = 0;
    if (w >= A.base[1]) r = 1;
    if (w >= A.base[2]) r = 2;
    if (w >= A.base[3]) r = 3;
    if (w >= A.base[4]) r = 4;
    int dst = w - A.base[r];
    const int* offp = off + A.offBase[r] + dst;
    int beg = __ldg(offp), end = __ldg(offp + 1);
    const float* aS = A.aS[r];
    const float* h = A.h[r];
    const int ss = A.ss[r];
    float2 ad = __ldg((const float2*)(A.aD[r] + (size_t)dst * A.sd[r]));

    float n00=0.f,n01=0.f,n02=0.f,n03=0.f,n10=0.f,n11=0.f,n12=0.f,n13=0.f,d0=0.f,d1=0.f;
    int j = beg;
    for (; j + 3 < end; j += 4) {
        int s0 = __ldg(csr + j),     s1 = __ldg(csr + j + 1);
        int s2 = __ldg(csr + j + 2), s3 = __ldg(csr + j + 3);
        float2 a0 = __ldg((const float2*)(aS + (size_t)s0 * ss));
        float2 a1 = __ldg((const float2*)(aS + (size_t)s1 * ss));
        float2 a2 = __ldg((const float2*)(aS + (size_t)s2 * ss));
        float2 a3 = __ldg((const float2*)(aS + (size_t)s3 * ss));
        float4 v0 = __ldg((const float4*)(h + (size_t)s0 * HID) + lane);
        float4 v1 = __ldg((const float4*)(h + (size_t)s1 * HID) + lane);
        float4 v2 = __ldg((const float4*)(h + (size_t)s2 * HID) + lane);
        float4 v3 = __ldg((const float4*)(h + (size_t)s3 * HID) + lane);
        float e00 = lexp(a0.x, ad.x), e01 = lexp(a0.y, ad.y);
        float e10 = lexp(a1.x, ad.x), e11 = lexp(a1.y, ad.y);
        float e20 = lexp(a2.x, ad.x), e21 = lexp(a2.y, ad.y);
        float e30 = lexp(a3.x, ad.x), e31 = lexp(a3.y, ad.y);
        d0 += (e00 + e10) + (e20 + e30);
        d1 += (e01 + e11) + (e21 + e31);
        n00 += e00*v0.x + e10*v1.x + e20*v2.x + e30*v3.x;
        n01 += e00*v0.y + e10*v1.y + e20*v2.y + e30*v3.y;
        n02 += e00*v0.z + e10*v1.z + e20*v2.z + e30*v3.z;
        n03 += e00*v0.w + e10*v1.w + e20*v2.w + e30*v3.w;
        n10 += e01*v0.x + e11*v1.x + e21*v2.x + e31*v3.x;
        n11 += e01*v0.y + e11*v1.y + e21*v2.y + e31*v3.y;
        n12 += e01*v0.z + e11*v1.z + e21*v2.z + e31*v3.z;
        n13 += e01*v0.w + e11*v1.w + e21*v2.w + e31*v3.w;
    }
    for (; j < end; j++) {
        int s0 = __ldg(csr + j);
        float2 a0 = __ldg((const float2*)(aS + (size_t)s0 * ss));
        float4 v0 = __ldg((const float4*)(h + (size_t)s0 * HID) + lane);
        float e0 = lexp(a0.x, ad.x), e1 = lexp(a0.y, ad.y);
        d0 += e0; d1 += e1;
        n00 += e0*v0.x; n01 += e0*v0.y; n02 += e0*v0.z; n03 += e0*v0.w;
        n10 += e1*v0.x; n11 += e1*v0.y; n12 += e1*v0.z; n13 += e1*v0.w;
    }
    float i0 = 1.f / (d0 + 1e-16f), i1 = 1.f / (d1 + 1e-16f);
    size_t base = (size_t)dst * A.accStride[r] + A.colOfs[r] + lane * 4;
    store4_split(A.acch[r] + base, A.accl[r] + base,
                 n00*i0, n01*i0, n02*i0, n03*i0);
    store4_split(A.acch[r] + base + 128, A.accl[r] + base + 128,
                 n10*i1, n11*i1, n12*i1, n13*i1);
}

// ================= host =================
extern "C" void kernel_launch(void* const* d_in, const int* in_sizes, int n_in,
                              void* d_out, int out_size)
{
    const float* post_cls = (const float*)d_in[0];
    const float* user_x   = (const float*)d_in[1];
    const float* Wpost    = (const float*)d_in[3];
    const float* bpost    = (const float*)d_in[4];
    const float* Wuser    = (const float*)d_in[5];
    const float* buser    = (const float*)d_in[6];
    const float* gWsrc    = (const float*)d_in[9];
    const float* gWdst    = (const float*)d_in[10];
    const float* gasrc    = (const float*)d_in[11];
    const float* gadst    = (const float*)d_in[12];
    const float* gbias    = (const float*)d_in[13];
    const float* Wc1      = (const float*)d_in[14];
    const float* bc1      = (const float*)d_in[15];
    const float* Wc2      = (const float*)d_in[16];
    const float* bc2      = (const float*)d_in[17];
    const int* e_src[4] = { (const int*)d_in[18], (const int*)d_in[20],
                            (const int*)d_in[24], (const int*)d_in[26] };
    const int* e_dst[4] = { (const int*)d_in[19], (const int*)d_in[21],
                            (const int*)d_in[25], (const int*)d_in[27] };
    const int  e_cnt[4] = { in_sizes[18], in_sizes[20], in_sizes[24], in_sizes[26] };

    static bool attr_done = false;
    if (!attr_done) {
        cudaFuncSetAttribute(hgemm_b, cudaFuncAttributeMaxDynamicSharedMemorySize, HG_SMEM);
        attr_done = true;
    }

    float *hAu, *hBu, *hBp, *aU, *aP, *aU2, *aP2, *uU, *uP, *bcb, *wt, *cv;
    bf16 *accUH,*accUL,*accPH,*accPL;
    bf16 *BuH,*BuL,*BpH,*BpL,*WuH,*WuL;
    int *cnt, *off, *cur, *csr, *bsum;
    cudaGetSymbolAddress((void**)&hAu, g_hA_user);
    cudaGetSymbolAddress((void**)&hBu, g_hB_user);
    cudaGetSymbolAddress((void**)&hBp, g_hB_post);
    cudaGetSymbolAddress((void**)&accUH, g_accUH); cudaGetSymbolAddress((void**)&accUL, g_accUL);
    cudaGetSymbolAddress((void**)&accPH, g_accPH); cudaGetSymbolAddress((void**)&accPL, g_accPL);
    cudaGetSymbolAddress((void**)&BuH, g_BuH); cudaGetSymbolAddress((void**)&BuL, g_BuL);
    cudaGetSymbolAddress((void**)&BpH, g_BpH); cudaGetSymbolAddress((void**)&BpL, g_BpL);
    cudaGetSymbolAddress((void**)&WuH, g_WuserH); cudaGetSymbolAddress((void**)&WuL, g_WuserL);
    cudaGetSymbolAddress((void**)&aU, g_aU); cudaGetSymbolAddress((void**)&aP, g_aP);
    cudaGetSymbolAddress((void**)&aU2, g_aU2); cudaGetSymbolAddress((void**)&aP2, g_aP2);
    cudaGetSymbolAddress((void**)&uU, g_uU); cudaGetSymbolAddress((void**)&uP, g_uP);
    cudaGetSymbolAddress((void**)&bcb, g_bc);
    cudaGetSymbolAddress((void**)&wt, g_wt); cudaGetSymbolAddress((void**)&cv, g_cv);
    cudaGetSymbolAddress((void**)&cnt, g_cnt);
    cudaGetSymbolAddress((void**)&off, g_off);
    cudaGetSymbolAddress((void**)&cur, g_cur);
    cudaGetSymbolAddress((void**)&csr, g_csr);
    cudaGetSymbolAddress((void**)&bsum, g_bsum);

    const int RB4[4] = { 0, 50000, 100000, 200000 };
    const int NC4 = 300001;

    E5 e;
    {
        int run = 0;
        for (int r = 0; r < 4; r++) {
            e.src[r] = e_src[r]; e.dst[r] = e_dst[r]; e.rb[r] = RB4[r];
            e.ebase[r] = run; run += e_cnt[r];
        }
        e.ebase[4] = run;
        e.ebase[5] = run;
        e.src[4] = e_src[3]; e.dst[4] = e_dst[3]; e.rb[4] = RB4[3];
    }

    // ---- fork s2 immediately: CSR build + layer-weight pack ----
    cudaEventRecord(g_evF, 0);
    cudaStreamWaitEvent(g_s2, g_evF, 0);
    hist_all<<<(e.ebase[5] + 255)/256, 256, 0, g_s2>>>(e, cnt);
    const int NB = (NC4 + SCAN_CHUNK - 1) / SCAN_CHUNK;
    scan_block_kernel<<<NB, 256, 0, g_s2>>>(cnt, off, bsum, NC4);
    scan_top_kernel<<<1, 128, 0, g_s2>>>(bsum, NB);
    scan_add_kernel<<<NB, 256, 0, g_s2>>>(off, cur, bsum, NC4);
    csr_scatter_all<<<(e.ebase[5] + 255)/256, 256, 0, g_s2>>>(e, cur, csr);
    cudaEventRecord(g_evJ, g_s2);
    pack_layerW<<<(3*128*512 + 255)/256, 256, 0, g_s2>>>(gWsrc, BuH, BuL, BpH, BpL);
    cudaEventRecord(g_evPack, g_s2);

    // ---- main: precompute + w~ fold ----
    precompute_all<<<23 + 32, 256>>>(gWsrc, gWdst, gasrc, gadst, gbias,
                                     uU, uP, bcb, Wuser, WuH, WuL);
    fold_wtilde<<<13, 256>>>(Wpost, bpost, uP, wt, cv);
    cudaEventRecord(g_evW, 0);

    const int CU = (NUSER + 127) / 128, CP = (NPOST + 127) / 128;

    // ---- s2: l0 post alphas (needs only w~) ----
    cudaStreamWaitEvent(g_s2, g_evW, 0);
    alpha_post0<<<((size_t)NPOST*32 + 255)/256, 256, 0, g_s2>>>(post_cls, wt, cv, aP, NPOST);
    cudaEventRecord(g_evAP0, g_s2);

    // ---- main: user projection + fused l=0 user alphas ----
    {
        GSeg s0;
        s0.A = user_x; s0.Bh = WuH; s0.Bl = WuL; s0.bias = buser;
        s0.C = hAu; s0.uvec = uU; s0.aout = aU;
        s0.M = NUSER; s0.K = 64; s0.relu = 0; s0.nv = 12; s0.ctaBase = 0; s0.abf = 0;
        GSeg s1 = s0; s1.ctaBase = CU;
        GSeg s2 = s0; s2.ctaBase = CU;
        hgemm_b<<<CU, 256, HG_SMEM>>>(s0, s1, s2);
    }

    // ---- main: unified layer-0 aggregation (all 4 live relations) ----
    cudaStreamWaitEvent(0, g_evJ, 0);
    cudaStreamWaitEvent(0, g_evAP0, 0);
    {
        AggAll A;
        // pub user->post
        A.aS[0] = aU + 0;  A.aD[0] = aP + 2; A.h[0] = hAu;
        A.acch[0] = accPH; A.accl[0] = accPL;
        A.ss[0] = 12; A.sd[0] = 6; A.accStride[0] = 512; A.colOfs[0] = 0;   A.offBase[0] = RB4[0];
        // rep user->post
        A.aS[1] = aU + 2;  A.aD[1] = aP + 4; A.h[1] = hAu;
        A.acch[1] = accPH; A.accl[1] = accPL;
        A.ss[1] = 12; A.sd[1] = 6; A.accStride[1] = 512; A.colOfs[1] = 256; A.offBase[1] = RB4[1];
        // int user->user
        A.aS[2] = aU + 4;  A.aD[2] = aU + 8;  A.h[2] = hAu;
        A.acch[2] = accUH; A.accl[2] = accUL;
        A.ss[2] = 12; A.sd[2] = 12; A.accStride[2] = 512; A.colOfs[2] = 0;  A.offBase[2] = RB4[2];
        // fol user->user
        A.aS[3] = aU + 6;  A.aD[3] = aU + 10; A.h[3] = hAu;
        A.acch[3] = accUH; A.accl[3] = accUL;
        A.ss[3] = 12; A.sd[3] = 12; A.accStride[3] = 512; A.colOfs[3] = 256; A.offBase[3] = RB4[3];
        A.aS[4] = A.aS[3]; A.aD[4] = A.aD[3]; A.h[4] = A.h[3];
        A.acch[4] = A.acch[3]; A.accl[4] = A.accl[3];
        A.ss[4] = 12; A.sd[4] = 12; A.accStride[4] = 512; A.colOfs[4] = 256; A.offBase[4] = RB4[3];
        A.base[0] = 0; A.base[1] = 50000; A.base[2] = 100000;
        A.base[3] = 200000; A.base[4] = 300000; A.base[5] = 300000;
        agg_all<<<((size_t)300000*32 + 255)/256, 256>>>(A, off, csr);
    }
    cudaEventRecord(g_evAgg0, 0);

    // ---- s2: gemm0-post (concurrent with main's gemm0-user) ----
    cudaStreamWaitEvent(g_s2, g_evAgg0, 0);
    {
        GSeg s0;
        s0.Abh = accPH; s0.Abl = accPL; s0.Bh = BpH; s0.Bl = BpL;
        s0.bias = bcb + 1*HID; s0.C = hBp; s0.uvec = uP + (size_t)8*HID; s0.aout = aP2;
        s0.M = NPOST; s0.K = 512; s0.relu = 1; s0.nv = 4; s0.ctaBase = 0; s0.abf = 1;
        GSeg s1 = s0; s1.ctaBase = CP;
        GSeg s2 = s0; s2.ctaBase = CP;
        hgemm_b<<<CP, 256, HG_SMEM, g_s2>>>(s0, s1, s2);
    }
    cudaEventRecord(g_evPost, g_s2);

    // ---- main: gemm0-user (no WAR: l1 alphas go to aU2) ----
    cudaStreamWaitEvent(0, g_evPack, 0);
    {
        GSeg s0;
        s0.Abh = accUH; s0.Abl = accUL; s0.Bh = BuH; s0.Bl = BuL;
        s0.bias = bcb + 0*HID; s0.C = hBu; s0.uvec = uU + (size_t)12*HID; s0.aout = aU2;
        s0.M = NUSER; s0.K = 512; s0.relu = 1; s0.nv = 4; s0.ctaBase = 0; s0.abf = 1;
        GSeg s1 = s0; s1.ctaBase = CU;
        GSeg s2 = s0; s2.ctaBase = CU;
        hgemm_b<<<CU, 256, HG_SMEM>>>(s0, s1, s2);
    }

    // ---- layer 1 on main (joins post chain) ----
    cudaStreamWaitEvent(0, g_evPost, 0);
    {
        AggAll A;
        A.aS[0] = aU2 + 0; A.aD[0] = aP2 + 0; A.h[0] = hBu;
        A.acch[0] = accPH; A.accl[0] = accPL;
        A.ss[0] = 4; A.sd[0] = 4; A.accStride[0] = 512; A.colOfs[0] = 0;   A.offBase[0] = RB4[0];
        A.aS[1] = aU2 + 2; A.aD[1] = aP2 + 2; A.h[1] = hBu;
        A.acch[1] = accPH; A.accl[1] = accPL;
        A.ss[1] = 4; A.sd[1] = 4; A.accStride[1] = 512; A.colOfs[1] = 256; A.offBase[1] = RB4[1];
        for (int r = 2; r < 5; r++) {
            A.aS[r] = A.aS[1]; A.aD[r] = A.aD[1]; A.h[r] = A.h[1];
            A.acch[r] = A.acch[1]; A.accl[r] = A.accl[1];
            A.ss[r] = 4; A.sd[r] = 4; A.accStride[r] = 512; A.colOfs[r] = 256; A.offBase[r] = RB4[1];
        }
        A.base[0] = 0; A.base[1] = 50000; A.base[2] = 100000;
        A.base[3] = 100000; A.base[4] = 100000; A.base[5] = 100000;
        agg_all<<<((size_t)100000*32 + 255)/256, 256>>>(A, off, csr);
    }
    {
        GSeg s0;
        s0.Abh = accPH; s0.Abl = accPL;
        s0.Bh = BpH + (size_t)128*512; s0.Bl = BpL + (size_t)128*512;
        s0.bias = bcb + 4*HID; s0.C = hBp; s0.uvec = uP; s0.aout = aP2;
        s0.M = NPOST; s0.K = 512; s0.relu = 1; s0.nv = 0; s0.ctaBase = 0; s0.abf = 1;
        s0.cW1 = Wc1; s0.cW2 = Wc2; s0.cB1 = bc1; s0.cB2 = bc2;
        s0.cOut = (float*)d_out; s0.clf = 1;
        GSeg s1 = s0; s1.ctaBase = CP;
        GSeg s2 = s0; s2.ctaBase = CP;
        hgemm_b<<<CP, 256, HG_SMEM>>>(s0, s1, s2);
    }
}